// round 15
// baseline (speedup 1.0000x reference)
#include <cuda_runtime.h>
#include <cuda_fp16.h>
#include <cstdint>

#define N_MAX 50000
#define E_MAX 1600000
#define HDIM  128
#define SA    136   // padded smem row stride (halves): 272B, 16B-aligned, conflict-free

// ---------------- static scratch ----------------
__device__ __half g_hA[(size_t)N_MAX * HDIM];
__device__ __half g_hB[(size_t)N_MAX * HDIM];
__device__ __half g_Wh[3 * HDIM * HDIM];        // enc2, gcn, dec1 weights in fp16
__device__ float  g_ew[E_MAX];
__device__ int    g_rank[E_MAX];                // within-dst-node rank (from pass1's atomic)
__device__ unsigned long long g_pack[N_MAX];    // [40:64) edge count, [0:40) ew sum (x 2^20 fixed)
                                                // zero-init at load; scan3m re-zeroes each launch
__device__ float  g_dis[N_MAX];
__device__ int    g_rowptr[N_MAX + 1];
__device__ int2   g_epack[E_MAX];               // (src, norm bits), grouped by dst
__device__ int    g_blocksum[1024];

// ---------------- preprocessing ----------------
// ONE packed 64-bit atomic per edge; the returned old value's count field is
// this edge's rank within its destination node — saved for pass2 (no atomic there).
__global__ void edge_pass1(const int* __restrict__ ei, const float4* __restrict__ attr, int E) {
    int e = blockIdx.x * blockDim.x + threadIdx.x;
    if (e >= E) return;
    int c = ei[E + e];
    float a = attr[e].w;
    float ew = 1.f / (a * a);
    g_ew[e] = ew;
    unsigned long long v = (1ull << 40) | (unsigned long long)__float2uint_rn(ew * 1048576.f);
    unsigned long long old = atomicAdd(&g_pack[c], v);
    g_rank[e] = (int)(old >> 40);
}

__global__ void scan1(int n) {
    __shared__ int s[1024];
    int tid = threadIdx.x;
    int i = blockIdx.x * 1024 + tid;
    int v = (i < n) ? (int)(g_pack[i] >> 40) : 0;
    s[tid] = v;
    __syncthreads();
    for (int off = 1; off < 1024; off <<= 1) {
        int t = (tid >= off) ? s[tid - off] : 0;
        __syncthreads();
        s[tid] += t;
        __syncthreads();
    }
    if (i < n) g_rowptr[i + 1] = s[tid];
    if (tid == 1023) g_blocksum[blockIdx.x] = s[1023];
}

// merged scan2+scan3 (+ g_pack re-zero)
__global__ void scan3m(int n) {
    __shared__ int s[64];
    int tid = threadIdx.x;
    int chunk = blockIdx.x >> 2;          // 256-node block -> 1024-chunk index
    if (tid < 64) s[tid] = (tid < chunk) ? g_blocksum[tid] : 0;
    __syncthreads();
    if (tid < 32) {
        int v = s[tid] + s[tid + 32];
        #pragma unroll
        for (int off = 16; off; off >>= 1) v += __shfl_down_sync(0xffffffffu, v, off);
        if (tid == 0) s[0] = v;
    }
    __syncthreads();
    int pre = s[0];
    int i = blockIdx.x * 256 + tid;
    if (i >= n) return;
    g_rowptr[i + 1] += pre;
    if (i == 0) g_rowptr[0] = 0;
    float degw = (float)(g_pack[i] & ((1ull << 40) - 1)) * (1.f / 1048576.f);
    g_dis[i] = rsqrtf(degw + 1.0f);
    g_pack[i] = 0ull;                      // restore zero state for next launch
}

// No atomics: position comes from the rank captured in pass1.
__global__ void edge_pass2(const int* __restrict__ ei, int E) {
    int e = blockIdx.x * blockDim.x + threadIdx.x;
    if (e >= E) return;
    int r = ei[e];
    int c = ei[E + e];
    float nm = g_dis[r] * g_ew[e] * g_dis[c];
    int pos = g_rowptr[c] + g_rank[e];
    g_epack[pos] = make_int2(r, __float_as_int(nm));
}

// ---------------- weight conversion fp32 -> fp16 ----------------
__global__ void cvt_w(const float* __restrict__ W0, const float* __restrict__ W1,
                      const float* __restrict__ W2) {
    int i = blockIdx.x * blockDim.x + threadIdx.x;
    if (i >= HDIM * HDIM) return;
    g_Wh[i]                   = __float2half(W0[i]);
    g_Wh[HDIM * HDIM + i]     = __float2half(W1[i]);
    g_Wh[2 * HDIM * HDIM + i] = __float2half(W2[i]);
}

// ---------------- shared MMA helpers ----------------
__device__ __forceinline__ uint32_t smem_u32(const void* p) {
    return (uint32_t)__cvta_generic_to_shared(p);
}
__device__ __forceinline__ void mma16816(float* c, const uint32_t* a, const uint32_t* b) {
    asm volatile("mma.sync.aligned.m16n8k16.row.col.f32.f16.f16.f32 "
                 "{%0,%1,%2,%3}, {%4,%5,%6,%7}, {%8,%9}, {%0,%1,%2,%3};"
                 : "+f"(c[0]), "+f"(c[1]), "+f"(c[2]), "+f"(c[3])
                 : "r"(a[0]), "r"(a[1]), "r"(a[2]), "r"(a[3]), "r"(b[0]), "r"(b[1]));
}

__device__ __forceinline__ void load_W_tile(__half* Bs, const __half* __restrict__ W, int tid) {
    #pragma unroll
    for (int l = 0; l < 8; l++) {
        int i = tid + l * 256;
        int r = i >> 4, c = (i & 15) << 3;
        *(uint4*)&Bs[r * SA + c] = *(const uint4*)&W[r * HDIM + c];
    }
}

// generic mainloop: warp computes rows [wm, wm+32) x cols [wn, wn+64)
__device__ __forceinline__ void mma_loop_w(const __half* As, const __half* Bs,
                                           float acc[2][8][4], int wm, int wn, int lane) {
    const int lr = lane & 15, lc = (lane >> 4) << 3;
    #pragma unroll
    for (int kt = 0; kt < 128; kt += 16) {
        uint32_t a[2][4];
        #pragma unroll
        for (int im = 0; im < 2; im++) {
            uint32_t ad = smem_u32(&As[(wm + im * 16 + lr) * SA + kt + lc]);
            asm volatile("ldmatrix.sync.aligned.m8n8.x4.shared.b16 {%0,%1,%2,%3}, [%4];"
                         : "=r"(a[im][0]), "=r"(a[im][1]), "=r"(a[im][2]), "=r"(a[im][3])
                         : "r"(ad));
        }
        #pragma unroll
        for (int nb = 0; nb < 4; nb++) {
            uint32_t b[4];
            uint32_t ad = smem_u32(&Bs[(kt + lr) * SA + wn + nb * 16 + lc]);
            asm volatile("ldmatrix.sync.aligned.m8n8.x4.trans.shared.b16 {%0,%1,%2,%3}, [%4];"
                         : "=r"(b[0]), "=r"(b[1]), "=r"(b[2]), "=r"(b[3])
                         : "r"(ad));
            #pragma unroll
            for (int im = 0; im < 2; im++) {
                mma16816(acc[im][nb * 2 + 0], a[im], &b[0]);
                mma16816(acc[im][nb * 2 + 1], a[im], &b[2]);
            }
        }
    }
}

__device__ __forceinline__ void mma_loop(const __half* As, const __half* Bs,
                                         float acc[2][8][4], int warp, int lane) {
    mma_loop_w(As, Bs, acc, (warp & 3) * 32, (warp >> 2) * 64, lane);
}

__device__ __forceinline__ uint2 pack4h(float x, float y, float z, float w) {
    __half2 lo = __floats2half2_rn(x, y);
    __half2 hi = __floats2half2_rn(z, w);
    return make_uint2(*(uint32_t*)&lo, *(uint32_t*)&hi);
}

// ---------------- MP GEMM: BM=256, 512 threads, 16 warps (8xM, 2xN) --------
__global__ void __launch_bounds__(512)
gemm_h2(const __half* __restrict__ A, const __half* __restrict__ W,
        const float* __restrict__ bias, __half* __restrict__ C, int M, int doRelu) {
    extern __shared__ __half sm[];
    __half* As = sm;              // 256 x SA
    __half* Bs = sm + 256 * SA;   // 128 x SA (W tile, [k][n])
    const int tid = threadIdx.x;
    const int m0 = blockIdx.x * 256;

    // W tile: 2048 uint4 over 512 threads -> 4 iters
    #pragma unroll
    for (int l = 0; l < 4; l++) {
        int i = tid + l * 512;
        int r = i >> 4, c = (i & 15) << 3;
        *(uint4*)&Bs[r * SA + c] = *(const uint4*)&W[r * HDIM + c];
    }
    // A tile: 4096 uint4 over 512 threads -> 8 iters
    #pragma unroll
    for (int l = 0; l < 8; l++) {
        int i = tid + l * 512;
        int r = i >> 4, c = (i & 15) << 3;
        uint4 v = make_uint4(0, 0, 0, 0);
        if (m0 + r < M) v = *(const uint4*)&A[(size_t)(m0 + r) * HDIM + c];
        *(uint4*)&As[r * SA + c] = v;
    }
    __syncthreads();

    const int warp = tid >> 5, lane = tid & 31;
    const int wm = (warp & 7) * 32;    // 8 warps along M (32 rows each)
    const int wn = (warp >> 3) * 64;   // 2 warps along N (64 cols each)
    float acc[2][8][4];
    #pragma unroll
    for (int i = 0; i < 2; i++)
        #pragma unroll
        for (int j = 0; j < 8; j++)
            #pragma unroll
            for (int q = 0; q < 4; q++) acc[i][j][q] = 0.f;
    mma_loop_w(As, Bs, acc, wm, wn, lane);

    const int r0 = lane >> 2, cq = (lane & 3) * 2;
    #pragma unroll
    for (int im = 0; im < 2; im++) {
        #pragma unroll
        for (int nf = 0; nf < 8; nf++) {
            int nn = wn + nf * 8 + cq;
            float b0 = bias[nn], b1 = bias[nn + 1];
            float v0 = acc[im][nf][0] + b0, v1 = acc[im][nf][1] + b1;
            float v2 = acc[im][nf][2] + b0, v3 = acc[im][nf][3] + b1;
            if (doRelu) {
                v0 = fmaxf(v0, 0.f); v1 = fmaxf(v1, 0.f);
                v2 = fmaxf(v2, 0.f); v3 = fmaxf(v3, 0.f);
            }
            int g0 = m0 + wm + im * 16 + r0;
            int g1 = g0 + 8;
            if (g0 < M) {
                __half2 p = __floats2half2_rn(v0, v1);
                *(__half2*)(C + (size_t)g0 * HDIM + nn) = p;
            }
            if (g1 < M) {
                __half2 p = __floats2half2_rn(v2, v3);
                *(__half2*)(C + (size_t)g1 * HDIM + nn) = p;
            }
        }
    }
}

// ---------------- aggregation (fp16 features, fp32 accum) -------------------
// warp per destination node; software-pipelined edge metadata.
// MEASURED-BEST loop (rounds 2/9/11) — do not hand-restructure; ptxas schedules it.
__global__ void agg_h(const __half* __restrict__ Hin, __half* __restrict__ Z, int n) {
    int w = (blockIdx.x * blockDim.x + threadIdx.x) >> 5;
    int lane = threadIdx.x & 31;
    if (w >= n) return;
    float d = g_dis[w];
    float d2 = d * d;
    uint2 raw = *(const uint2*)(Hin + (size_t)w * HDIM + lane * 4);
    float2 f0 = __half22float2(*(__half2*)&raw.x);
    float2 f1 = __half22float2(*(__half2*)&raw.y);
    float4 acc = make_float4(f0.x * d2, f0.y * d2, f1.x * d2, f1.y * d2);
    int p = g_rowptr[w];
    int pe = g_rowptr[w + 1];
    int2 ep;
    if (p < pe) ep = g_epack[p];
    while (p < pe) {
        int2 cur = ep;
        int pn = p + 1;
        if (pn < pe) ep = g_epack[pn];
        float nm = __int_as_float(cur.y);
        uint2 v = *(const uint2*)(Hin + (size_t)cur.x * HDIM + lane * 4);
        float2 a0 = __half22float2(*(__half2*)&v.x);
        float2 a1 = __half22float2(*(__half2*)&v.y);
        acc.x += nm * a0.x; acc.y += nm * a0.y;
        acc.z += nm * a1.x; acc.w += nm * a1.y;
        p = pn;
    }
    __half2 lo = __floats2half2_rn(acc.x, acc.y);
    __half2 hi = __floats2half2_rn(acc.z, acc.w);
    *(uint2*)(Z + (size_t)w * HDIM + lane * 4) = make_uint2(*(uint32_t*)&lo, *(uint32_t*)&hi);
}

// ---------------- fused encoder: h = (relu(in@W1+b1)) @ W2 + b2 -------------
__global__ void __launch_bounds__(256)
fused_enc(const float* __restrict__ x, const float* __restrict__ xm,
          const float* __restrict__ W1, const float* __restrict__ b1,
          const __half* __restrict__ W2h, const float* __restrict__ b2,
          __half* __restrict__ Hout, int M) {
    extern __shared__ __half sm[];
    __half* As = sm;
    __half* Bs = sm + 128 * SA;
    __shared__ float Ws1[16][HDIM];
    __shared__ float bs1[HDIM];
    __shared__ float ins[128][17];
    const int tid = threadIdx.x;
    const int warp = tid >> 5, lane = tid & 31;
    const int m0 = blockIdx.x * 128;

    load_W_tile(Bs, W2h, tid);
    for (int i = tid; i < 16 * HDIM; i += 256) ((float*)Ws1)[i] = W1[i];
    if (tid < HDIM) bs1[tid] = b1[tid];
    #pragma unroll
    for (int l = 0; l < 8; l++) {
        int idx = tid + l * 256;
        int i = idx >> 4, k = idx & 15;
        int gn = m0 + i;
        float v = 0.f;
        if (gn < M) v = (k < 8) ? x[gn * 9 + k] : xm[gn * 9 + (k - 8)];
        ins[i][k] = v;
    }
    __syncthreads();

    int j = lane * 4;
    #pragma unroll 1
    for (int it = 0; it < 16; it++) {
        int lrow = it * 8 + warp;
        float4 acc = *(float4*)&bs1[j];
        #pragma unroll
        for (int k = 0; k < 16; k++) {
            float hv = ins[lrow][k];
            float4 w = *(float4*)&Ws1[k][j];
            acc.x += hv * w.x; acc.y += hv * w.y; acc.z += hv * w.z; acc.w += hv * w.w;
        }
        uint2 pk = pack4h(fmaxf(acc.x, 0.f), fmaxf(acc.y, 0.f),
                          fmaxf(acc.z, 0.f), fmaxf(acc.w, 0.f));
        *(uint2*)&As[lrow * SA + j] = pk;
    }
    __syncthreads();

    float acc[2][8][4];
    #pragma unroll
    for (int i = 0; i < 2; i++)
        #pragma unroll
        for (int jj = 0; jj < 8; jj++)
            #pragma unroll
            for (int q = 0; q < 4; q++) acc[i][jj][q] = 0.f;
    mma_loop(As, Bs, acc, warp, lane);

    const int wm = (warp & 3) * 32, wn = (warp >> 2) * 64;
    const int r0 = lane >> 2, cq = (lane & 3) * 2;
    #pragma unroll
    for (int im = 0; im < 2; im++) {
        #pragma unroll
        for (int nf = 0; nf < 8; nf++) {
            int nn = wn + nf * 8 + cq;
            float b0 = b2[nn], b1v = b2[nn + 1];
            float v0 = acc[im][nf][0] + b0, v1 = acc[im][nf][1] + b1v;
            float v2 = acc[im][nf][2] + b0, v3 = acc[im][nf][3] + b1v;
            int g0 = m0 + wm + im * 16 + r0;
            int g1 = g0 + 8;
            if (g0 < M) {
                __half2 p = __floats2half2_rn(v0, v1);
                *(__half2*)(Hout + (size_t)g0 * HDIM + nn) = p;
            }
            if (g1 < M) {
                __half2 p = __floats2half2_rn(v2, v3);
                *(__half2*)(Hout + (size_t)g1 * HDIM + nn) = p;
            }
        }
    }
}

// ---------------- fused decoder: out = relu(h@W1+b1) @ W2 + b2 --------------
__global__ void __launch_bounds__(256)
fused_dec(const __half* __restrict__ Hin, const __half* __restrict__ W1h,
          const float* __restrict__ b1, const float* __restrict__ W2,
          const float* __restrict__ b2, float* __restrict__ out, int M) {
    extern __shared__ __half sm[];
    __half* As = sm;
    __half* Bs = sm + 128 * SA;
    __shared__ float Ws2[HDIM * 3];
    const int tid = threadIdx.x;
    const int warp = tid >> 5, lane = tid & 31;
    const int m0 = blockIdx.x * 128;

    load_W_tile(Bs, W1h, tid);
    for (int i = tid; i < HDIM * 3; i += 256) Ws2[i] = W2[i];
    #pragma unroll
    for (int l = 0; l < 8; l++) {
        int i = tid + l * 256;
        int r = i >> 4, c = (i & 15) << 3;
        uint4 v = make_uint4(0, 0, 0, 0);
        if (m0 + r < M) v = *(const uint4*)&Hin[(size_t)(m0 + r) * HDIM + c];
        *(uint4*)&As[r * SA + c] = v;
    }
    __syncthreads();

    float acc[2][8][4];
    #pragma unroll
    for (int i = 0; i < 2; i++)
        #pragma unroll
        for (int jj = 0; jj < 8; jj++)
            #pragma unroll
            for (int q = 0; q < 4; q++) acc[i][jj][q] = 0.f;
    mma_loop(As, Bs, acc, warp, lane);
    __syncthreads();   // done reading As; reuse it for dec1 output

    const int wm = (warp & 3) * 32, wn = (warp >> 2) * 64;
    const int r0 = lane >> 2, cq = (lane & 3) * 2;
    #pragma unroll
    for (int im = 0; im < 2; im++) {
        #pragma unroll
        for (int nf = 0; nf < 8; nf++) {
            int nn = wn + nf * 8 + cq;
            float b0 = b1[nn], b1v = b1[nn + 1];
            float v0 = fmaxf(acc[im][nf][0] + b0, 0.f);
            float v1 = fmaxf(acc[im][nf][1] + b1v, 0.f);
            float v2 = fmaxf(acc[im][nf][2] + b0, 0.f);
            float v3 = fmaxf(acc[im][nf][3] + b1v, 0.f);
            int l0 = wm + im * 16 + r0;
            __half2 p0 = __floats2half2_rn(v0, v1);
            __half2 p1 = __floats2half2_rn(v2, v3);
            *(__half2*)&As[l0 * SA + nn] = p0;
            *(__half2*)&As[(l0 + 8) * SA + nn] = p1;
        }
    }
    __syncthreads();

    // final 128 -> 3 projection: warp per node, 16 iterations
    #pragma unroll 1
    for (int it = 0; it < 16; it++) {
        int lrow = it * 8 + warp;
        int gn = m0 + lrow;
        uint2 raw = *(uint2*)&As[lrow * SA + lane * 4];
        float2 f0 = __half22float2(*(__half2*)&raw.x);
        float2 f1 = __half22float2(*(__half2*)&raw.y);
        float hv[4] = {f0.x, f0.y, f1.x, f1.y};
        float a0 = 0.f, a1 = 0.f, a2 = 0.f;
        #pragma unroll
        for (int q = 0; q < 4; q++) {
            int k = lane * 4 + q;
            a0 += hv[q] * Ws2[k * 3 + 0];
            a1 += hv[q] * Ws2[k * 3 + 1];
            a2 += hv[q] * Ws2[k * 3 + 2];
        }
        #pragma unroll
        for (int off = 16; off; off >>= 1) {
            a0 += __shfl_xor_sync(0xffffffffu, a0, off);
            a1 += __shfl_xor_sync(0xffffffffu, a1, off);
            a2 += __shfl_xor_sync(0xffffffffu, a2, off);
        }
        if (lane == 0 && gn < M) {
            out[gn * 3 + 0] = a0 + b2[0];
            out[gn * 3 + 1] = a1 + b2[1];
            out[gn * 3 + 2] = a2 + b2[2];
        }
    }
}

// ---------------- launch ----------------
extern "C" void kernel_launch(void* const* d_in, const int* in_sizes, int n_in,
                              void* d_out, int out_size) {
    const float* x     = (const float*)d_in[0];
    const float* xm    = (const float*)d_in[1];
    const int*   ei    = (const int*)  d_in[2];
    const float* attr  = (const float*)d_in[3];
    const float* Wenc1 = (const float*)d_in[5];
    const float* benc1 = (const float*)d_in[6];
    const float* Wenc2 = (const float*)d_in[7];
    const float* benc2 = (const float*)d_in[8];
    const float* Wgcn  = (const float*)d_in[9];
    const float* bgcn  = (const float*)d_in[10];
    const float* Wdec1 = (const float*)d_in[11];
    const float* bdec1 = (const float*)d_in[12];
    const float* Wdec2 = (const float*)d_in[13];
    const float* bdec2 = (const float*)d_in[14];

    int n = in_sizes[0] / 9;
    int E = in_sizes[2] / 2;
    float* out = (float*)d_out;

    __half *hA, *hB, *Wh;
    cudaGetSymbolAddress((void**)&hA, g_hA);
    cudaGetSymbolAddress((void**)&hB, g_hB);
    cudaGetSymbolAddress((void**)&Wh, g_Wh);

    const int GEMM_SMEM  = 2 * 128 * SA * (int)sizeof(__half);  // 69632 (enc/dec)
    const int GEMM2_SMEM = 3 * 128 * SA * (int)sizeof(__half);  // 104448 (BM=256 MP gemm)

    static int s_init = 0;
    static cudaStream_t s_pre;
    static cudaEvent_t s_evF, s_evJ;
    if (!s_init) {
        cudaFuncSetAttribute(gemm_h2,   cudaFuncAttributeMaxDynamicSharedMemorySize, GEMM2_SMEM);
        cudaFuncSetAttribute(fused_enc, cudaFuncAttributeMaxDynamicSharedMemorySize, GEMM_SMEM);
        cudaFuncSetAttribute(fused_dec, cudaFuncAttributeMaxDynamicSharedMemorySize, GEMM_SMEM);
        cudaStreamCreateWithFlags(&s_pre, cudaStreamNonBlocking);
        cudaEventCreateWithFlags(&s_evF, cudaEventDisableTiming);
        cudaEventCreateWithFlags(&s_evJ, cudaEventDisableTiming);
        s_init = 1;
    }

    // ---- fork: CSR build on s_pre || encoder chain on stream 0 ----
    cudaEventRecord(s_evF, 0);
    cudaStreamWaitEvent(s_pre, s_evF, 0);

    edge_pass1<<<(E + 255) / 256, 256, 0, s_pre>>>(ei, (const float4*)attr, E);
    int NB = (n + 1023) / 1024;
    scan1<<<NB, 1024, 0, s_pre>>>(n);
    scan3m<<<(n + 255) / 256, 256, 0, s_pre>>>(n);
    edge_pass2<<<(E + 255) / 256, 256, 0, s_pre>>>(ei, E);
    cudaEventRecord(s_evJ, s_pre);

    cvt_w<<<(HDIM * HDIM + 255) / 256, 256>>>(Wenc2, Wgcn, Wdec1);
    int gB = (n + 127) / 128;
    fused_enc<<<gB, 256, GEMM_SMEM>>>(x, xm, Wenc1, benc1, Wh, benc2, hB, n);

    cudaStreamWaitEvent(0, s_evJ, 0);   // join before first agg

    // ---- MP: fixed buffers — h in hB, z scratch in hA ----
    int gB2 = (n + 255) / 256;
    for (int s = 0; s < 4; s++) {
        agg_h<<<(n * 32 + 511) / 512, 512>>>(hB, hA, n);
        gemm_h2<<<gB2, 512, GEMM2_SMEM>>>(hA, Wh + HDIM * HDIM, bgcn, hB, n, 1);
    }

    // decoder (fused dec1 GEMM + 128->3 projection)
    fused_dec<<<gB, 256, GEMM_SMEM>>>(hB, Wh + 2 * HDIM * HDIM, bdec1, Wdec2, bdec2, out, n);
}

// round 16
// speedup vs baseline: 1.0631x; 1.0631x over previous
#include <cuda_runtime.h>
#include <cuda_fp16.h>
#include <cstdint>

#define N_MAX 50000
#define E_MAX 1600000
#define HDIM  128
#define SA    136   // padded smem row stride (halves): 272B, 16B-aligned, conflict-free

// ---------------- static scratch ----------------
__device__ __half g_hA[(size_t)N_MAX * HDIM];
__device__ __half g_hB[(size_t)N_MAX * HDIM];
__device__ __half g_Wh[3 * HDIM * HDIM];        // enc2, gcn, dec1 weights in fp16
__device__ float  g_ew[E_MAX];
__device__ int    g_rank[E_MAX];                // within-dst-node rank (from pass1's atomic)
__device__ unsigned long long g_pack[N_MAX];    // [40:64) edge count, [0:40) ew sum (x 2^20 fixed)
                                                // zero-init at load; scan3m re-zeroes each launch
__device__ float  g_dis[N_MAX];
__device__ int    g_rowptr[N_MAX + 1];
__device__ int2   g_epack[E_MAX];               // (src, norm bits), grouped by dst
__device__ int    g_blocksum[1024];

// ---------------- preprocessing ----------------
// ONE packed 64-bit atomic per edge; the returned old value's count field is
// this edge's rank within its destination node — saved for pass2 (no atomic there).
__global__ void edge_pass1(const int* __restrict__ ei, const float4* __restrict__ attr, int E) {
    int e = blockIdx.x * blockDim.x + threadIdx.x;
    if (e >= E) return;
    int c = ei[E + e];
    float a = attr[e].w;
    float ew = 1.f / (a * a);
    g_ew[e] = ew;
    unsigned long long v = (1ull << 40) | (unsigned long long)__float2uint_rn(ew * 1048576.f);
    unsigned long long old = atomicAdd(&g_pack[c], v);
    g_rank[e] = (int)(old >> 40);
}

__global__ void scan1(int n) {
    __shared__ int s[1024];
    int tid = threadIdx.x;
    int i = blockIdx.x * 1024 + tid;
    int v = (i < n) ? (int)(g_pack[i] >> 40) : 0;
    s[tid] = v;
    __syncthreads();
    for (int off = 1; off < 1024; off <<= 1) {
        int t = (tid >= off) ? s[tid - off] : 0;
        __syncthreads();
        s[tid] += t;
        __syncthreads();
    }
    if (i < n) g_rowptr[i + 1] = s[tid];
    if (tid == 1023) g_blocksum[blockIdx.x] = s[1023];
}

// merged scan2+scan3 (+ g_pack re-zero): each 256-node block lies in exactly one
// 1024-chunk, so the needed exclusive block-sum prefix is a <=64-entry reduction.
__global__ void scan3m(int n) {
    __shared__ int s[64];
    int tid = threadIdx.x;
    int chunk = blockIdx.x >> 2;          // 256-node block -> 1024-chunk index
    if (tid < 64) s[tid] = (tid < chunk) ? g_blocksum[tid] : 0;
    __syncthreads();
    if (tid < 32) {
        int v = s[tid] + s[tid + 32];
        #pragma unroll
        for (int off = 16; off; off >>= 1) v += __shfl_down_sync(0xffffffffu, v, off);
        if (tid == 0) s[0] = v;
    }
    __syncthreads();
    int pre = s[0];
    int i = blockIdx.x * 256 + tid;
    if (i >= n) return;
    g_rowptr[i + 1] += pre;
    if (i == 0) g_rowptr[0] = 0;
    float degw = (float)(g_pack[i] & ((1ull << 40) - 1)) * (1.f / 1048576.f);
    g_dis[i] = rsqrtf(degw + 1.0f);
    g_pack[i] = 0ull;                      // restore zero state for next launch
}

// No atomics: position comes from the rank captured in pass1.
__global__ void edge_pass2(const int* __restrict__ ei, int E) {
    int e = blockIdx.x * blockDim.x + threadIdx.x;
    if (e >= E) return;
    int r = ei[e];
    int c = ei[E + e];
    float nm = g_dis[r] * g_ew[e] * g_dis[c];
    int pos = g_rowptr[c] + g_rank[e];
    g_epack[pos] = make_int2(r, __float_as_int(nm));
}

// ---------------- weight conversion fp32 -> fp16 ----------------
__global__ void cvt_w(const float* __restrict__ W0, const float* __restrict__ W1,
                      const float* __restrict__ W2) {
    int i = blockIdx.x * blockDim.x + threadIdx.x;
    if (i >= HDIM * HDIM) return;
    g_Wh[i]                   = __float2half(W0[i]);
    g_Wh[HDIM * HDIM + i]     = __float2half(W1[i]);
    g_Wh[2 * HDIM * HDIM + i] = __float2half(W2[i]);
}

// ---------------- shared MMA helpers ----------------
__device__ __forceinline__ uint32_t smem_u32(const void* p) {
    return (uint32_t)__cvta_generic_to_shared(p);
}
__device__ __forceinline__ void mma16816(float* c, const uint32_t* a, const uint32_t* b) {
    asm volatile("mma.sync.aligned.m16n8k16.row.col.f32.f16.f16.f32 "
                 "{%0,%1,%2,%3}, {%4,%5,%6,%7}, {%8,%9}, {%0,%1,%2,%3};"
                 : "+f"(c[0]), "+f"(c[1]), "+f"(c[2]), "+f"(c[3])
                 : "r"(a[0]), "r"(a[1]), "r"(a[2]), "r"(a[3]), "r"(b[0]), "r"(b[1]));
}

__device__ __forceinline__ void load_W_tile(__half* Bs, const __half* __restrict__ W, int tid) {
    #pragma unroll
    for (int l = 0; l < 8; l++) {
        int i = tid + l * 256;
        int r = i >> 4, c = (i & 15) << 3;
        *(uint4*)&Bs[r * SA + c] = *(const uint4*)&W[r * HDIM + c];
    }
}

__device__ __forceinline__ void mma_loop(const __half* As, const __half* Bs,
                                         float acc[2][8][4], int warp, int lane) {
    const int wm = (warp & 3) * 32;
    const int wn = (warp >> 2) * 64;
    const int lr = lane & 15, lc = (lane >> 4) << 3;
    #pragma unroll
    for (int kt = 0; kt < 128; kt += 16) {
        uint32_t a[2][4];
        #pragma unroll
        for (int im = 0; im < 2; im++) {
            uint32_t ad = smem_u32(&As[(wm + im * 16 + lr) * SA + kt + lc]);
            asm volatile("ldmatrix.sync.aligned.m8n8.x4.shared.b16 {%0,%1,%2,%3}, [%4];"
                         : "=r"(a[im][0]), "=r"(a[im][1]), "=r"(a[im][2]), "=r"(a[im][3])
                         : "r"(ad));
        }
        #pragma unroll
        for (int nb = 0; nb < 4; nb++) {
            uint32_t b[4];
            uint32_t ad = smem_u32(&Bs[(kt + lr) * SA + wn + nb * 16 + lc]);
            asm volatile("ldmatrix.sync.aligned.m8n8.x4.trans.shared.b16 {%0,%1,%2,%3}, [%4];"
                         : "=r"(b[0]), "=r"(b[1]), "=r"(b[2]), "=r"(b[3])
                         : "r"(ad));
            #pragma unroll
            for (int im = 0; im < 2; im++) {
                mma16816(acc[im][nb * 2 + 0], a[im], &b[0]);
                mma16816(acc[im][nb * 2 + 1], a[im], &b[2]);
            }
        }
    }
}

__device__ __forceinline__ uint2 pack4h(float x, float y, float z, float w) {
    __half2 lo = __floats2half2_rn(x, y);
    __half2 hi = __floats2half2_rn(z, w);
    return make_uint2(*(uint32_t*)&lo, *(uint32_t*)&hi);
}

// ---------------- GEMM: C = act(A[M,128] @ W[128,128] + b), fp16 in/out -----
__global__ void __launch_bounds__(256)
gemm_h(const __half* __restrict__ A, const __half* __restrict__ W,
       const float* __restrict__ bias, __half* __restrict__ C, int M, int doRelu) {
    extern __shared__ __half sm[];
    __half* As = sm;              // 128 x SA
    __half* Bs = sm + 128 * SA;   // 128 x SA (W tile, [k][n])
    const int tid = threadIdx.x;
    const int m0 = blockIdx.x * 128;

    load_W_tile(Bs, W, tid);
    #pragma unroll
    for (int l = 0; l < 8; l++) {
        int i = tid + l * 256;
        int r = i >> 4, c = (i & 15) << 3;
        uint4 v = make_uint4(0, 0, 0, 0);
        if (m0 + r < M) v = *(const uint4*)&A[(size_t)(m0 + r) * HDIM + c];
        *(uint4*)&As[r * SA + c] = v;
    }
    __syncthreads();

    const int warp = tid >> 5, lane = tid & 31;
    float acc[2][8][4];
    #pragma unroll
    for (int i = 0; i < 2; i++)
        #pragma unroll
        for (int j = 0; j < 8; j++)
            #pragma unroll
            for (int q = 0; q < 4; q++) acc[i][j][q] = 0.f;
    mma_loop(As, Bs, acc, warp, lane);

    const int wm = (warp & 3) * 32, wn = (warp >> 2) * 64;
    const int r0 = lane >> 2, cq = (lane & 3) * 2;
    #pragma unroll
    for (int im = 0; im < 2; im++) {
        #pragma unroll
        for (int nf = 0; nf < 8; nf++) {
            int nn = wn + nf * 8 + cq;
            float b0 = bias[nn], b1 = bias[nn + 1];
            float v0 = acc[im][nf][0] + b0, v1 = acc[im][nf][1] + b1;
            float v2 = acc[im][nf][2] + b0, v3 = acc[im][nf][3] + b1;
            if (doRelu) {
                v0 = fmaxf(v0, 0.f); v1 = fmaxf(v1, 0.f);
                v2 = fmaxf(v2, 0.f); v3 = fmaxf(v3, 0.f);
            }
            int g0 = m0 + wm + im * 16 + r0;
            int g1 = g0 + 8;
            if (g0 < M) {
                __half2 p = __floats2half2_rn(v0, v1);
                *(__half2*)(C + (size_t)g0 * HDIM + nn) = p;
            }
            if (g1 < M) {
                __half2 p = __floats2half2_rn(v2, v3);
                *(__half2*)(C + (size_t)g1 * HDIM + nn) = p;
            }
        }
    }
}

// ---------------- aggregation (fp16 features, fp32 accum) -------------------
// warp per destination node; software-pipelined edge metadata.
// MEASURED-BEST loop (rounds 2/9/11) — do not hand-restructure; ptxas schedules it.
__global__ void agg_h(const __half* __restrict__ Hin, __half* __restrict__ Z, int n) {
    int w = (blockIdx.x * blockDim.x + threadIdx.x) >> 5;
    int lane = threadIdx.x & 31;
    if (w >= n) return;
    float d = g_dis[w];
    float d2 = d * d;
    uint2 raw = *(const uint2*)(Hin + (size_t)w * HDIM + lane * 4);
    float2 f0 = __half22float2(*(__half2*)&raw.x);
    float2 f1 = __half22float2(*(__half2*)&raw.y);
    float4 acc = make_float4(f0.x * d2, f0.y * d2, f1.x * d2, f1.y * d2);
    int p = g_rowptr[w];
    int pe = g_rowptr[w + 1];
    int2 ep;
    if (p < pe) ep = g_epack[p];
    while (p < pe) {
        int2 cur = ep;
        int pn = p + 1;
        if (pn < pe) ep = g_epack[pn];
        float nm = __int_as_float(cur.y);
        uint2 v = *(const uint2*)(Hin + (size_t)cur.x * HDIM + lane * 4);
        float2 a0 = __half22float2(*(__half2*)&v.x);
        float2 a1 = __half22float2(*(__half2*)&v.y);
        acc.x += nm * a0.x; acc.y += nm * a0.y;
        acc.z += nm * a1.x; acc.w += nm * a1.y;
        p = pn;
    }
    __half2 lo = __floats2half2_rn(acc.x, acc.y);
    __half2 hi = __floats2half2_rn(acc.z, acc.w);
    *(uint2*)(Z + (size_t)w * HDIM + lane * 4) = make_uint2(*(uint32_t*)&lo, *(uint32_t*)&hi);
}

// ---------------- fused encoder: h = (relu(in@W1+b1)) @ W2 + b2 -------------
__global__ void __launch_bounds__(256)
fused_enc(const float* __restrict__ x, const float* __restrict__ xm,
          const float* __restrict__ W1, const float* __restrict__ b1,
          const __half* __restrict__ W2h, const float* __restrict__ b2,
          __half* __restrict__ Hout, int M) {
    extern __shared__ __half sm[];
    __half* As = sm;
    __half* Bs = sm + 128 * SA;
    __shared__ float Ws1[16][HDIM];
    __shared__ float bs1[HDIM];
    __shared__ float ins[128][17];
    const int tid = threadIdx.x;
    const int warp = tid >> 5, lane = tid & 31;
    const int m0 = blockIdx.x * 128;

    load_W_tile(Bs, W2h, tid);
    for (int i = tid; i < 16 * HDIM; i += 256) ((float*)Ws1)[i] = W1[i];
    if (tid < HDIM) bs1[tid] = b1[tid];
    #pragma unroll
    for (int l = 0; l < 8; l++) {
        int idx = tid + l * 256;
        int i = idx >> 4, k = idx & 15;
        int gn = m0 + i;
        float v = 0.f;
        if (gn < M) v = (k < 8) ? x[gn * 9 + k] : xm[gn * 9 + (k - 8)];
        ins[i][k] = v;
    }
    __syncthreads();

    int j = lane * 4;
    #pragma unroll 1
    for (int it = 0; it < 16; it++) {
        int lrow = it * 8 + warp;
        float4 acc = *(float4*)&bs1[j];
        #pragma unroll
        for (int k = 0; k < 16; k++) {
            float hv = ins[lrow][k];
            float4 w = *(float4*)&Ws1[k][j];
            acc.x += hv * w.x; acc.y += hv * w.y; acc.z += hv * w.z; acc.w += hv * w.w;
        }
        uint2 pk = pack4h(fmaxf(acc.x, 0.f), fmaxf(acc.y, 0.f),
                          fmaxf(acc.z, 0.f), fmaxf(acc.w, 0.f));
        *(uint2*)&As[lrow * SA + j] = pk;
    }
    __syncthreads();

    float acc[2][8][4];
    #pragma unroll
    for (int i = 0; i < 2; i++)
        #pragma unroll
        for (int jj = 0; jj < 8; jj++)
            #pragma unroll
            for (int q = 0; q < 4; q++) acc[i][jj][q] = 0.f;
    mma_loop(As, Bs, acc, warp, lane);

    const int wm = (warp & 3) * 32, wn = (warp >> 2) * 64;
    const int r0 = lane >> 2, cq = (lane & 3) * 2;
    #pragma unroll
    for (int im = 0; im < 2; im++) {
        #pragma unroll
        for (int nf = 0; nf < 8; nf++) {
            int nn = wn + nf * 8 + cq;
            float b0 = b2[nn], b1v = b2[nn + 1];
            float v0 = acc[im][nf][0] + b0, v1 = acc[im][nf][1] + b1v;
            float v2 = acc[im][nf][2] + b0, v3 = acc[im][nf][3] + b1v;
            int g0 = m0 + wm + im * 16 + r0;
            int g1 = g0 + 8;
            if (g0 < M) {
                __half2 p = __floats2half2_rn(v0, v1);
                *(__half2*)(Hout + (size_t)g0 * HDIM + nn) = p;
            }
            if (g1 < M) {
                __half2 p = __floats2half2_rn(v2, v3);
                *(__half2*)(Hout + (size_t)g1 * HDIM + nn) = p;
            }
        }
    }
}

// ---------------- fused decoder: out = relu(h@W1+b1) @ W2 + b2 --------------
__global__ void __launch_bounds__(256)
fused_dec(const __half* __restrict__ Hin, const __half* __restrict__ W1h,
          const float* __restrict__ b1, const float* __restrict__ W2,
          const float* __restrict__ b2, float* __restrict__ out, int M) {
    extern __shared__ __half sm[];
    __half* As = sm;
    __half* Bs = sm + 128 * SA;
    __shared__ float Ws2[HDIM * 3];
    const int tid = threadIdx.x;
    const int warp = tid >> 5, lane = tid & 31;
    const int m0 = blockIdx.x * 128;

    load_W_tile(Bs, W1h, tid);
    for (int i = tid; i < HDIM * 3; i += 256) Ws2[i] = W2[i];
    #pragma unroll
    for (int l = 0; l < 8; l++) {
        int i = tid + l * 256;
        int r = i >> 4, c = (i & 15) << 3;
        uint4 v = make_uint4(0, 0, 0, 0);
        if (m0 + r < M) v = *(const uint4*)&Hin[(size_t)(m0 + r) * HDIM + c];
        *(uint4*)&As[r * SA + c] = v;
    }
    __syncthreads();

    float acc[2][8][4];
    #pragma unroll
    for (int i = 0; i < 2; i++)
        #pragma unroll
        for (int jj = 0; jj < 8; jj++)
            #pragma unroll
            for (int q = 0; q < 4; q++) acc[i][jj][q] = 0.f;
    mma_loop(As, Bs, acc, warp, lane);
    __syncthreads();   // done reading As; reuse it for dec1 output

    const int wm = (warp & 3) * 32, wn = (warp >> 2) * 64;
    const int r0 = lane >> 2, cq = (lane & 3) * 2;
    #pragma unroll
    for (int im = 0; im < 2; im++) {
        #pragma unroll
        for (int nf = 0; nf < 8; nf++) {
            int nn = wn + nf * 8 + cq;
            float b0 = b1[nn], b1v = b1[nn + 1];
            float v0 = fmaxf(acc[im][nf][0] + b0, 0.f);
            float v1 = fmaxf(acc[im][nf][1] + b1v, 0.f);
            float v2 = fmaxf(acc[im][nf][2] + b0, 0.f);
            float v3 = fmaxf(acc[im][nf][3] + b1v, 0.f);
            int l0 = wm + im * 16 + r0;
            __half2 p0 = __floats2half2_rn(v0, v1);
            __half2 p1 = __floats2half2_rn(v2, v3);
            *(__half2*)&As[l0 * SA + nn] = p0;
            *(__half2*)&As[(l0 + 8) * SA + nn] = p1;
        }
    }
    __syncthreads();

    // final 128 -> 3 projection: warp per node, 16 iterations
    #pragma unroll 1
    for (int it = 0; it < 16; it++) {
        int lrow = it * 8 + warp;
        int gn = m0 + lrow;
        uint2 raw = *(uint2*)&As[lrow * SA + lane * 4];
        float2 f0 = __half22float2(*(__half2*)&raw.x);
        float2 f1 = __half22float2(*(__half2*)&raw.y);
        float hv[4] = {f0.x, f0.y, f1.x, f1.y};
        float a0 = 0.f, a1 = 0.f, a2 = 0.f;
        #pragma unroll
        for (int q = 0; q < 4; q++) {
            int k = lane * 4 + q;
            a0 += hv[q] * Ws2[k * 3 + 0];
            a1 += hv[q] * Ws2[k * 3 + 1];
            a2 += hv[q] * Ws2[k * 3 + 2];
        }
        #pragma unroll
        for (int off = 16; off; off >>= 1) {
            a0 += __shfl_xor_sync(0xffffffffu, a0, off);
            a1 += __shfl_xor_sync(0xffffffffu, a1, off);
            a2 += __shfl_xor_sync(0xffffffffu, a2, off);
        }
        if (lane == 0 && gn < M) {
            out[gn * 3 + 0] = a0 + b2[0];
            out[gn * 3 + 1] = a1 + b2[1];
            out[gn * 3 + 2] = a2 + b2[2];
        }
    }
}

// ---------------- launch ----------------
extern "C" void kernel_launch(void* const* d_in, const int* in_sizes, int n_in,
                              void* d_out, int out_size) {
    const float* x     = (const float*)d_in[0];
    const float* xm    = (const float*)d_in[1];
    const int*   ei    = (const int*)  d_in[2];
    const float* attr  = (const float*)d_in[3];
    const float* Wenc1 = (const float*)d_in[5];
    const float* benc1 = (const float*)d_in[6];
    const float* Wenc2 = (const float*)d_in[7];
    const float* benc2 = (const float*)d_in[8];
    const float* Wgcn  = (const float*)d_in[9];
    const float* bgcn  = (const float*)d_in[10];
    const float* Wdec1 = (const float*)d_in[11];
    const float* bdec1 = (const float*)d_in[12];
    const float* Wdec2 = (const float*)d_in[13];
    const float* bdec2 = (const float*)d_in[14];

    int n = in_sizes[0] / 9;
    int E = in_sizes[2] / 2;
    float* out = (float*)d_out;

    __half *hA, *hB, *Wh;
    cudaGetSymbolAddress((void**)&hA, g_hA);
    cudaGetSymbolAddress((void**)&hB, g_hB);
    cudaGetSymbolAddress((void**)&Wh, g_Wh);

    const int GEMM_SMEM = 2 * 128 * SA * (int)sizeof(__half);  // 69632

    static int s_init = 0;
    static cudaStream_t s_pre;
    static cudaEvent_t s_evF, s_evJ;
    if (!s_init) {
        cudaFuncSetAttribute(gemm_h,    cudaFuncAttributeMaxDynamicSharedMemorySize, GEMM_SMEM);
        cudaFuncSetAttribute(fused_enc, cudaFuncAttributeMaxDynamicSharedMemorySize, GEMM_SMEM);
        cudaFuncSetAttribute(fused_dec, cudaFuncAttributeMaxDynamicSharedMemorySize, GEMM_SMEM);
        cudaStreamCreateWithFlags(&s_pre, cudaStreamNonBlocking);
        cudaEventCreateWithFlags(&s_evF, cudaEventDisableTiming);
        cudaEventCreateWithFlags(&s_evJ, cudaEventDisableTiming);
        s_init = 1;
    }

    // ---- fork: CSR build on s_pre || encoder chain on stream 0 ----
    // g_pack arrives zeroed (zero-init at load; scan3m re-zeroes each launch).
    // Chain: pass1 (atomic, captures ranks) -> scan1 -> scan3m -> pass2 (atomic-free).
    cudaEventRecord(s_evF, 0);
    cudaStreamWaitEvent(s_pre, s_evF, 0);

    edge_pass1<<<(E + 255) / 256, 256, 0, s_pre>>>(ei, (const float4*)attr, E);
    int NB = (n + 1023) / 1024;
    scan1<<<NB, 1024, 0, s_pre>>>(n);
    scan3m<<<(n + 255) / 256, 256, 0, s_pre>>>(n);
    edge_pass2<<<(E + 255) / 256, 256, 0, s_pre>>>(ei, E);
    cudaEventRecord(s_evJ, s_pre);

    cvt_w<<<(HDIM * HDIM + 255) / 256, 256>>>(Wenc2, Wgcn, Wdec1);
    int gB = (n + 127) / 128;
    fused_enc<<<gB, 256, GEMM_SMEM>>>(x, xm, Wenc1, benc1, Wh, benc2, hB, n);

    cudaStreamWaitEvent(0, s_evJ, 0);   // join before first agg

    // ---- MP: fixed buffers — h in hB, z scratch in hA ----
    for (int s = 0; s < 4; s++) {
        agg_h<<<(n * 32 + 255) / 256, 256>>>(hB, hA, n);
        gemm_h<<<gB, 256, GEMM_SMEM>>>(hA, Wh + HDIM * HDIM, bgcn, hB, n, 1);
    }

    // decoder (fused dec1 GEMM + 128->3 projection)
    fused_dec<<<gB, 256, GEMM_SMEM>>>(hB, Wh + 2 * HDIM * HDIM, bdec1, Wdec2, bdec2, out, n);
}

// round 17
// speedup vs baseline: 1.0702x; 1.0067x over previous
#include <cuda_runtime.h>
#include <cuda_fp16.h>
#include <cstdint>

#define N_MAX 50000
#define E_MAX 1600000
#define HDIM  128
#define SA    136   // padded smem row stride (halves): 272B, 16B-aligned, conflict-free

// ---------------- static scratch ----------------
__device__ __half g_hA[(size_t)N_MAX * HDIM];
__device__ __half g_hB[(size_t)N_MAX * HDIM];
__device__ __half g_Wh[2 * HDIM * HDIM];        // gcn, dec1 in fp16 (enc2 converted in-kernel)
__device__ float  g_ew[E_MAX];
__device__ int    g_rank[E_MAX];                // within-dst-node rank (from pass1's atomic)
__device__ unsigned long long g_pack[N_MAX];    // [40:64) edge count, [0:40) ew sum (x 2^20 fixed)
                                                // zero-init at load; scan3m re-zeroes each launch
__device__ float  g_dis[N_MAX];
__device__ int    g_rowptr[N_MAX + 1];
__device__ int2   g_epack[E_MAX];               // (src, norm bits), grouped by dst
__device__ int    g_blocksum[1024];

// ---------------- preprocessing ----------------
// ONE packed 64-bit atomic per edge; the returned old value's count field is
// this edge's rank within its destination node — saved for pass2 (no atomic there).
__global__ void edge_pass1(const int* __restrict__ ei, const float4* __restrict__ attr, int E) {
    int e = blockIdx.x * blockDim.x + threadIdx.x;
    if (e >= E) return;
    int c = ei[E + e];
    float a = attr[e].w;
    float ew = 1.f / (a * a);
    g_ew[e] = ew;
    unsigned long long v = (1ull << 40) | (unsigned long long)__float2uint_rn(ew * 1048576.f);
    unsigned long long old = atomicAdd(&g_pack[c], v);
    g_rank[e] = (int)(old >> 40);
}

__global__ void scan1(int n) {
    __shared__ int s[1024];
    int tid = threadIdx.x;
    int i = blockIdx.x * 1024 + tid;
    int v = (i < n) ? (int)(g_pack[i] >> 40) : 0;
    s[tid] = v;
    __syncthreads();
    for (int off = 1; off < 1024; off <<= 1) {
        int t = (tid >= off) ? s[tid - off] : 0;
        __syncthreads();
        s[tid] += t;
        __syncthreads();
    }
    if (i < n) g_rowptr[i + 1] = s[tid];
    if (tid == 1023) g_blocksum[blockIdx.x] = s[1023];
}

// merged scan2+scan3 (+ g_pack re-zero)
__global__ void scan3m(int n) {
    __shared__ int s[64];
    int tid = threadIdx.x;
    int chunk = blockIdx.x >> 2;          // 256-node block -> 1024-chunk index
    if (tid < 64) s[tid] = (tid < chunk) ? g_blocksum[tid] : 0;
    __syncthreads();
    if (tid < 32) {
        int v = s[tid] + s[tid + 32];
        #pragma unroll
        for (int off = 16; off; off >>= 1) v += __shfl_down_sync(0xffffffffu, v, off);
        if (tid == 0) s[0] = v;
    }
    __syncthreads();
    int pre = s[0];
    int i = blockIdx.x * 256 + tid;
    if (i >= n) return;
    g_rowptr[i + 1] += pre;
    if (i == 0) g_rowptr[0] = 0;
    float degw = (float)(g_pack[i] & ((1ull << 40) - 1)) * (1.f / 1048576.f);
    g_dis[i] = rsqrtf(degw + 1.0f);
    g_pack[i] = 0ull;                      // restore zero state for next launch
}

// No atomics: position comes from the rank captured in pass1.
__global__ void edge_pass2(const int* __restrict__ ei, int E) {
    int e = blockIdx.x * blockDim.x + threadIdx.x;
    if (e >= E) return;
    int r = ei[e];
    int c = ei[E + e];
    float nm = g_dis[r] * g_ew[e] * g_dis[c];
    int pos = g_rowptr[c] + g_rank[e];
    g_epack[pos] = make_int2(r, __float_as_int(nm));
}

// ---------------- weight conversion fp32 -> fp16 (gcn + dec1 only) ---------
__global__ void cvt_w2(const float* __restrict__ W1, const float* __restrict__ W2) {
    int i = blockIdx.x * blockDim.x + threadIdx.x;
    if (i >= HDIM * HDIM) return;
    g_Wh[i]               = __float2half(W1[i]);
    g_Wh[HDIM * HDIM + i] = __float2half(W2[i]);
}

// ---------------- shared MMA helpers ----------------
__device__ __forceinline__ uint32_t smem_u32(const void* p) {
    return (uint32_t)__cvta_generic_to_shared(p);
}
__device__ __forceinline__ void mma16816(float* c, const uint32_t* a, const uint32_t* b) {
    asm volatile("mma.sync.aligned.m16n8k16.row.col.f32.f16.f16.f32 "
                 "{%0,%1,%2,%3}, {%4,%5,%6,%7}, {%8,%9}, {%0,%1,%2,%3};"
                 : "+f"(c[0]), "+f"(c[1]), "+f"(c[2]), "+f"(c[3])
                 : "r"(a[0]), "r"(a[1]), "r"(a[2]), "r"(a[3]), "r"(b[0]), "r"(b[1]));
}

__device__ __forceinline__ void load_W_tile(__half* Bs, const __half* __restrict__ W, int tid) {
    #pragma unroll
    for (int l = 0; l < 8; l++) {
        int i = tid + l * 256;
        int r = i >> 4, c = (i & 15) << 3;
        *(uint4*)&Bs[r * SA + c] = *(const uint4*)&W[r * HDIM + c];
    }
}

// load W tile from fp32 source, converting to fp16 during the smem fill
__device__ __forceinline__ void load_W_tile_f32(__half* Bs, const float* __restrict__ W, int tid) {
    #pragma unroll
    for (int l = 0; l < 8; l++) {
        int i = tid + l * 256;
        int r = i >> 4, c = (i & 15) << 3;
        float4 w0 = *(const float4*)&W[r * HDIM + c];
        float4 w1 = *(const float4*)&W[r * HDIM + c + 4];
        __half2 h0 = __floats2half2_rn(w0.x, w0.y);
        __half2 h1 = __floats2half2_rn(w0.z, w0.w);
        __half2 h2 = __floats2half2_rn(w1.x, w1.y);
        __half2 h3 = __floats2half2_rn(w1.z, w1.w);
        uint4 pk = make_uint4(*(uint32_t*)&h0, *(uint32_t*)&h1,
                              *(uint32_t*)&h2, *(uint32_t*)&h3);
        *(uint4*)&Bs[r * SA + c] = pk;
    }
}

__device__ __forceinline__ void mma_loop(const __half* As, const __half* Bs,
                                         float acc[2][8][4], int warp, int lane) {
    const int wm = (warp & 3) * 32;
    const int wn = (warp >> 2) * 64;
    const int lr = lane & 15, lc = (lane >> 4) << 3;
    #pragma unroll
    for (int kt = 0; kt < 128; kt += 16) {
        uint32_t a[2][4];
        #pragma unroll
        for (int im = 0; im < 2; im++) {
            uint32_t ad = smem_u32(&As[(wm + im * 16 + lr) * SA + kt + lc]);
            asm volatile("ldmatrix.sync.aligned.m8n8.x4.shared.b16 {%0,%1,%2,%3}, [%4];"
                         : "=r"(a[im][0]), "=r"(a[im][1]), "=r"(a[im][2]), "=r"(a[im][3])
                         : "r"(ad));
        }
        #pragma unroll
        for (int nb = 0; nb < 4; nb++) {
            uint32_t b[4];
            uint32_t ad = smem_u32(&Bs[(kt + lr) * SA + wn + nb * 16 + lc]);
            asm volatile("ldmatrix.sync.aligned.m8n8.x4.trans.shared.b16 {%0,%1,%2,%3}, [%4];"
                         : "=r"(b[0]), "=r"(b[1]), "=r"(b[2]), "=r"(b[3])
                         : "r"(ad));
            #pragma unroll
            for (int im = 0; im < 2; im++) {
                mma16816(acc[im][nb * 2 + 0], a[im], &b[0]);
                mma16816(acc[im][nb * 2 + 1], a[im], &b[2]);
            }
        }
    }
}

__device__ __forceinline__ uint2 pack4h(float x, float y, float z, float w) {
    __half2 lo = __floats2half2_rn(x, y);
    __half2 hi = __floats2half2_rn(z, w);
    return make_uint2(*(uint32_t*)&lo, *(uint32_t*)&hi);
}

// ---------------- GEMM: C = act(A[M,128] @ W[128,128] + b), fp16 in/out -----
__global__ void __launch_bounds__(256)
gemm_h(const __half* __restrict__ A, const __half* __restrict__ W,
       const float* __restrict__ bias, __half* __restrict__ C, int M, int doRelu) {
    extern __shared__ __half sm[];
    __half* As = sm;              // 128 x SA
    __half* Bs = sm + 128 * SA;   // 128 x SA (W tile, [k][n])
    const int tid = threadIdx.x;
    const int m0 = blockIdx.x * 128;

    load_W_tile(Bs, W, tid);
    #pragma unroll
    for (int l = 0; l < 8; l++) {
        int i = tid + l * 256;
        int r = i >> 4, c = (i & 15) << 3;
        uint4 v = make_uint4(0, 0, 0, 0);
        if (m0 + r < M) v = *(const uint4*)&A[(size_t)(m0 + r) * HDIM + c];
        *(uint4*)&As[r * SA + c] = v;
    }
    __syncthreads();

    const int warp = tid >> 5, lane = tid & 31;
    float acc[2][8][4];
    #pragma unroll
    for (int i = 0; i < 2; i++)
        #pragma unroll
        for (int j = 0; j < 8; j++)
            #pragma unroll
            for (int q = 0; q < 4; q++) acc[i][j][q] = 0.f;
    mma_loop(As, Bs, acc, warp, lane);

    const int wm = (warp & 3) * 32, wn = (warp >> 2) * 64;
    const int r0 = lane >> 2, cq = (lane & 3) * 2;
    #pragma unroll
    for (int im = 0; im < 2; im++) {
        #pragma unroll
        for (int nf = 0; nf < 8; nf++) {
            int nn = wn + nf * 8 + cq;
            float b0 = bias[nn], b1 = bias[nn + 1];
            float v0 = acc[im][nf][0] + b0, v1 = acc[im][nf][1] + b1;
            float v2 = acc[im][nf][2] + b0, v3 = acc[im][nf][3] + b1;
            if (doRelu) {
                v0 = fmaxf(v0, 0.f); v1 = fmaxf(v1, 0.f);
                v2 = fmaxf(v2, 0.f); v3 = fmaxf(v3, 0.f);
            }
            int g0 = m0 + wm + im * 16 + r0;
            int g1 = g0 + 8;
            if (g0 < M) {
                __half2 p = __floats2half2_rn(v0, v1);
                *(__half2*)(C + (size_t)g0 * HDIM + nn) = p;
            }
            if (g1 < M) {
                __half2 p = __floats2half2_rn(v2, v3);
                *(__half2*)(C + (size_t)g1 * HDIM + nn) = p;
            }
        }
    }
}

// ---------------- aggregation (fp16 features, fp32 accum) -------------------
// warp per destination node; software-pipelined edge metadata.
// MEASURED-BEST loop (rounds 2/9/11) — do not hand-restructure; ptxas schedules it.
__global__ void agg_h(const __half* __restrict__ Hin, __half* __restrict__ Z, int n) {
    int w = (blockIdx.x * blockDim.x + threadIdx.x) >> 5;
    int lane = threadIdx.x & 31;
    if (w >= n) return;
    float d = g_dis[w];
    float d2 = d * d;
    uint2 raw = *(const uint2*)(Hin + (size_t)w * HDIM + lane * 4);
    float2 f0 = __half22float2(*(__half2*)&raw.x);
    float2 f1 = __half22float2(*(__half2*)&raw.y);
    float4 acc = make_float4(f0.x * d2, f0.y * d2, f1.x * d2, f1.y * d2);
    int p = g_rowptr[w];
    int pe = g_rowptr[w + 1];
    int2 ep;
    if (p < pe) ep = g_epack[p];
    while (p < pe) {
        int2 cur = ep;
        int pn = p + 1;
        if (pn < pe) ep = g_epack[pn];
        float nm = __int_as_float(cur.y);
        uint2 v = *(const uint2*)(Hin + (size_t)cur.x * HDIM + lane * 4);
        float2 a0 = __half22float2(*(__half2*)&v.x);
        float2 a1 = __half22float2(*(__half2*)&v.y);
        acc.x += nm * a0.x; acc.y += nm * a0.y;
        acc.z += nm * a1.x; acc.w += nm * a1.y;
        p = pn;
    }
    __half2 lo = __floats2half2_rn(acc.x, acc.y);
    __half2 hi = __floats2half2_rn(acc.z, acc.w);
    *(uint2*)(Z + (size_t)w * HDIM + lane * 4) = make_uint2(*(uint32_t*)&lo, *(uint32_t*)&hi);
}

// ---------------- fused encoder: h = (relu(in@W1+b1)) @ W2 + b2 -------------
// W2 taken directly in fp32 and converted during the smem tile fill —
// removes the cvt_w dependency from the stream-0 critical path.
__global__ void __launch_bounds__(256)
fused_enc(const float* __restrict__ x, const float* __restrict__ xm,
          const float* __restrict__ W1, const float* __restrict__ b1,
          const float* __restrict__ W2f, const float* __restrict__ b2,
          __half* __restrict__ Hout, int M) {
    extern __shared__ __half sm[];
    __half* As = sm;
    __half* Bs = sm + 128 * SA;
    __shared__ float Ws1[16][HDIM];
    __shared__ float bs1[HDIM];
    __shared__ float ins[128][17];
    const int tid = threadIdx.x;
    const int warp = tid >> 5, lane = tid & 31;
    const int m0 = blockIdx.x * 128;

    load_W_tile_f32(Bs, W2f, tid);
    for (int i = tid; i < 16 * HDIM; i += 256) ((float*)Ws1)[i] = W1[i];
    if (tid < HDIM) bs1[tid] = b1[tid];
    #pragma unroll
    for (int l = 0; l < 8; l++) {
        int idx = tid + l * 256;
        int i = idx >> 4, k = idx & 15;
        int gn = m0 + i;
        float v = 0.f;
        if (gn < M) v = (k < 8) ? x[gn * 9 + k] : xm[gn * 9 + (k - 8)];
        ins[i][k] = v;
    }
    __syncthreads();

    int j = lane * 4;
    #pragma unroll 1
    for (int it = 0; it < 16; it++) {
        int lrow = it * 8 + warp;
        float4 acc = *(float4*)&bs1[j];
        #pragma unroll
        for (int k = 0; k < 16; k++) {
            float hv = ins[lrow][k];
            float4 w = *(float4*)&Ws1[k][j];
            acc.x += hv * w.x; acc.y += hv * w.y; acc.z += hv * w.z; acc.w += hv * w.w;
        }
        uint2 pk = pack4h(fmaxf(acc.x, 0.f), fmaxf(acc.y, 0.f),
                          fmaxf(acc.z, 0.f), fmaxf(acc.w, 0.f));
        *(uint2*)&As[lrow * SA + j] = pk;
    }
    __syncthreads();

    float acc[2][8][4];
    #pragma unroll
    for (int i = 0; i < 2; i++)
        #pragma unroll
        for (int jj = 0; jj < 8; jj++)
            #pragma unroll
            for (int q = 0; q < 4; q++) acc[i][jj][q] = 0.f;
    mma_loop(As, Bs, acc, warp, lane);

    const int wm = (warp & 3) * 32, wn = (warp >> 2) * 64;
    const int r0 = lane >> 2, cq = (lane & 3) * 2;
    #pragma unroll
    for (int im = 0; im < 2; im++) {
        #pragma unroll
        for (int nf = 0; nf < 8; nf++) {
            int nn = wn + nf * 8 + cq;
            float b0 = b2[nn], b1v = b2[nn + 1];
            float v0 = acc[im][nf][0] + b0, v1 = acc[im][nf][1] + b1v;
            float v2 = acc[im][nf][2] + b0, v3 = acc[im][nf][3] + b1v;
            int g0 = m0 + wm + im * 16 + r0;
            int g1 = g0 + 8;
            if (g0 < M) {
                __half2 p = __floats2half2_rn(v0, v1);
                *(__half2*)(Hout + (size_t)g0 * HDIM + nn) = p;
            }
            if (g1 < M) {
                __half2 p = __floats2half2_rn(v2, v3);
                *(__half2*)(Hout + (size_t)g1 * HDIM + nn) = p;
            }
        }
    }
}

// ---------------- fused decoder: out = relu(h@W1+b1) @ W2 + b2 --------------
__global__ void __launch_bounds__(256)
fused_dec(const __half* __restrict__ Hin, const __half* __restrict__ W1h,
          const float* __restrict__ b1, const float* __restrict__ W2,
          const float* __restrict__ b2, float* __restrict__ out, int M) {
    extern __shared__ __half sm[];
    __half* As = sm;
    __half* Bs = sm + 128 * SA;
    __shared__ float Ws2[HDIM * 3];
    const int tid = threadIdx.x;
    const int warp = tid >> 5, lane = tid & 31;
    const int m0 = blockIdx.x * 128;

    load_W_tile(Bs, W1h, tid);
    for (int i = tid; i < HDIM * 3; i += 256) Ws2[i] = W2[i];
    #pragma unroll
    for (int l = 0; l < 8; l++) {
        int i = tid + l * 256;
        int r = i >> 4, c = (i & 15) << 3;
        uint4 v = make_uint4(0, 0, 0, 0);
        if (m0 + r < M) v = *(const uint4*)&Hin[(size_t)(m0 + r) * HDIM + c];
        *(uint4*)&As[r * SA + c] = v;
    }
    __syncthreads();

    float acc[2][8][4];
    #pragma unroll
    for (int i = 0; i < 2; i++)
        #pragma unroll
        for (int jj = 0; jj < 8; jj++)
            #pragma unroll
            for (int q = 0; q < 4; q++) acc[i][jj][q] = 0.f;
    mma_loop(As, Bs, acc, warp, lane);
    __syncthreads();   // done reading As; reuse it for dec1 output

    const int wm = (warp & 3) * 32, wn = (warp >> 2) * 64;
    const int r0 = lane >> 2, cq = (lane & 3) * 2;
    #pragma unroll
    for (int im = 0; im < 2; im++) {
        #pragma unroll
        for (int nf = 0; nf < 8; nf++) {
            int nn = wn + nf * 8 + cq;
            float b0 = b1[nn], b1v = b1[nn + 1];
            float v0 = fmaxf(acc[im][nf][0] + b0, 0.f);
            float v1 = fmaxf(acc[im][nf][1] + b1v, 0.f);
            float v2 = fmaxf(acc[im][nf][2] + b0, 0.f);
            float v3 = fmaxf(acc[im][nf][3] + b1v, 0.f);
            int l0 = wm + im * 16 + r0;
            __half2 p0 = __floats2half2_rn(v0, v1);
            __half2 p1 = __floats2half2_rn(v2, v3);
            *(__half2*)&As[l0 * SA + nn] = p0;
            *(__half2*)&As[(l0 + 8) * SA + nn] = p1;
        }
    }
    __syncthreads();

    // final 128 -> 3 projection: warp per node, 16 iterations
    #pragma unroll 1
    for (int it = 0; it < 16; it++) {
        int lrow = it * 8 + warp;
        int gn = m0 + lrow;
        uint2 raw = *(uint2*)&As[lrow * SA + lane * 4];
        float2 f0 = __half22float2(*(__half2*)&raw.x);
        float2 f1 = __half22float2(*(__half2*)&raw.y);
        float hv[4] = {f0.x, f0.y, f1.x, f1.y};
        float a0 = 0.f, a1 = 0.f, a2 = 0.f;
        #pragma unroll
        for (int q = 0; q < 4; q++) {
            int k = lane * 4 + q;
            a0 += hv[q] * Ws2[k * 3 + 0];
            a1 += hv[q] * Ws2[k * 3 + 1];
            a2 += hv[q] * Ws2[k * 3 + 2];
        }
        #pragma unroll
        for (int off = 16; off; off >>= 1) {
            a0 += __shfl_xor_sync(0xffffffffu, a0, off);
            a1 += __shfl_xor_sync(0xffffffffu, a1, off);
            a2 += __shfl_xor_sync(0xffffffffu, a2, off);
        }
        if (lane == 0 && gn < M) {
            out[gn * 3 + 0] = a0 + b2[0];
            out[gn * 3 + 1] = a1 + b2[1];
            out[gn * 3 + 2] = a2 + b2[2];
        }
    }
}

// ---------------- launch ----------------
extern "C" void kernel_launch(void* const* d_in, const int* in_sizes, int n_in,
                              void* d_out, int out_size) {
    const float* x     = (const float*)d_in[0];
    const float* xm    = (const float*)d_in[1];
    const int*   ei    = (const int*)  d_in[2];
    const float* attr  = (const float*)d_in[3];
    const float* Wenc1 = (const float*)d_in[5];
    const float* benc1 = (const float*)d_in[6];
    const float* Wenc2 = (const float*)d_in[7];
    const float* benc2 = (const float*)d_in[8];
    const float* Wgcn  = (const float*)d_in[9];
    const float* bgcn  = (const float*)d_in[10];
    const float* Wdec1 = (const float*)d_in[11];
    const float* bdec1 = (const float*)d_in[12];
    const float* Wdec2 = (const float*)d_in[13];
    const float* bdec2 = (const float*)d_in[14];

    int n = in_sizes[0] / 9;
    int E = in_sizes[2] / 2;
    float* out = (float*)d_out;

    __half *hA, *hB, *Wh;
    cudaGetSymbolAddress((void**)&hA, g_hA);
    cudaGetSymbolAddress((void**)&hB, g_hB);
    cudaGetSymbolAddress((void**)&Wh, g_Wh);

    const int GEMM_SMEM = 2 * 128 * SA * (int)sizeof(__half);  // 69632

    static int s_init = 0;
    static cudaStream_t s_pre, s_aux;
    static cudaEvent_t s_evF, s_evJ, s_evA;
    if (!s_init) {
        cudaFuncSetAttribute(gemm_h,    cudaFuncAttributeMaxDynamicSharedMemorySize, GEMM_SMEM);
        cudaFuncSetAttribute(fused_enc, cudaFuncAttributeMaxDynamicSharedMemorySize, GEMM_SMEM);
        cudaFuncSetAttribute(fused_dec, cudaFuncAttributeMaxDynamicSharedMemorySize, GEMM_SMEM);
        cudaStreamCreateWithFlags(&s_pre, cudaStreamNonBlocking);
        cudaStreamCreateWithFlags(&s_aux, cudaStreamNonBlocking);
        cudaEventCreateWithFlags(&s_evF, cudaEventDisableTiming);
        cudaEventCreateWithFlags(&s_evJ, cudaEventDisableTiming);
        cudaEventCreateWithFlags(&s_evA, cudaEventDisableTiming);
        s_init = 1;
    }

    // ---- fork: CSR build on s_pre || weight cvt on s_aux || encoder on 0 ----
    cudaEventRecord(s_evF, 0);
    cudaStreamWaitEvent(s_pre, s_evF, 0);
    cudaStreamWaitEvent(s_aux, s_evF, 0);

    edge_pass1<<<(E + 255) / 256, 256, 0, s_pre>>>(ei, (const float4*)attr, E);
    int NB = (n + 1023) / 1024;
    scan1<<<NB, 1024, 0, s_pre>>>(n);
    scan3m<<<(n + 255) / 256, 256, 0, s_pre>>>(n);
    edge_pass2<<<(E + 255) / 256, 256, 0, s_pre>>>(ei, E);
    cudaEventRecord(s_evJ, s_pre);

    cvt_w2<<<(HDIM * HDIM + 255) / 256, 256, 0, s_aux>>>(Wgcn, Wdec1);
    cudaEventRecord(s_evA, s_aux);

    int gB = (n + 127) / 128;
    fused_enc<<<gB, 256, GEMM_SMEM>>>(x, xm, Wenc1, benc1, Wenc2, benc2, hB, n);

    cudaStreamWaitEvent(0, s_evJ, 0);   // CSR ready
    cudaStreamWaitEvent(0, s_evA, 0);   // gcn/dec1 weights ready

    // ---- MP: fixed buffers — h in hB, z scratch in hA ----
    for (int s = 0; s < 4; s++) {
        agg_h<<<(n * 32 + 255) / 256, 256>>>(hB, hA, n);
        gemm_h<<<gB, 256, GEMM_SMEM>>>(hA, Wh, bgcn, hB, n, 1);
    }

    // decoder (fused dec1 GEMM + 128->3 projection)
    fused_dec<<<gB, 256, GEMM_SMEM>>>(hB, Wh + HDIM * HDIM, bdec1, Wdec2, bdec2, out, n);
}